// round 1
// baseline (speedup 1.0000x reference)
#include <cuda_runtime.h>
#include <cuda_bf16.h>

#define PP 5
#define BLK 256
#define UBV 0.5f
#define LBV 0.0f

__global__ __launch_bounds__(BLK) void portfolio_kernel(
    const float* __restrict__ x1,    // (B,)
    const float* __restrict__ x2,    // (B,5,5)
    const float* __restrict__ eps,   // (4,B,5)
    const float* __restrict__ W,     // (4,3,5,5)
    float* __restrict__ out_wealth,  // (B,)
    float* __restrict__ out_cov,     // (B,5,5)
    int B)
{
    __shared__ float s_w[75];            // W[3], 3 matrices of 5x5
    __shared__ float s_x2[BLK * 25];     // staged x2 rows, later reused for curr_cov
    __shared__ float s_eps[BLK * 5];     // staged eps[3] rows

    const int tid = threadIdx.x;
    const long long base = (long long)blockIdx.x * BLK;

    if (tid < 75) s_w[tid] = W[3 * 75 + tid];

    // Coalesced staging of this block's x2 tile and eps[3] tile
    const float* __restrict__ x2g = x2 + base * 25;
    #pragma unroll 4
    for (int j = tid; j < BLK * 25; j += BLK) s_x2[j] = x2g[j];
    const float* __restrict__ epsg = eps + (long long)3 * B * PP + base * PP;
    for (int j = tid; j < BLK * 5; j += BLK) s_eps[j] = epsg[j];
    __syncthreads();

    // Per-thread row into registers (stride-25 shared reads: conflict-free, 25 coprime 32)
    float m2[25];
    #pragma unroll
    for (int i = 0; i < 25; i++) m2[i] = s_x2[tid * 25 + i];
    float e[PP];
    #pragma unroll
    for (int i = 0; i < PP; i++) e[i] = s_eps[tid * PP + i];

    // Ce = x2 @ eps3
    float ce[PP];
    #pragma unroll
    for (int i = 0; i < PP; i++) {
        float s = 0.f;
        #pragma unroll
        for (int j = 0; j < PP; j++) s += m2[i * PP + j] * e[j];
        ce[i] = s;
    }

    // R = mu + Ce ; h = R then 3x tanh(h @ W_l^T)
    float r[PP], h[PP];
    #pragma unroll
    for (int i = 0; i < PP; i++) { r[i] = 0.01f + ce[i]; h[i] = r[i]; }
    #pragma unroll
    for (int l = 0; l < 3; l++) {
        float t[PP];
        #pragma unroll
        for (int i = 0; i < PP; i++) {
            float s = 0.f;
            #pragma unroll
            for (int j = 0; j < PP; j++) s += h[j] * s_w[l * 25 + i * PP + j];
            t[i] = tanhf(s);
        }
        #pragma unroll
        for (int i = 0; i < PP; i++) h[i] = t[i];
    }

    // softmax with max subtraction (jax.nn.softmax)
    float mx = h[0];
    #pragma unroll
    for (int i = 1; i < PP; i++) mx = fmaxf(mx, h[i]);
    float ssum = 0.f;
    float wgt[PP];
    #pragma unroll
    for (int i = 0; i < PP; i++) { wgt[i] = __expf(h[i] - mx); ssum += wgt[i]; }
    #pragma unroll
    for (int i = 0; i < PP; i++) wgt[i] /= ssum;

    // --- rebalance: exact replication of the 8-iter scan ---
    float oldw[PP], nw[PP];
    #pragma unroll
    for (int i = 0; i < PP; i++) {
        oldw[i] = wgt[i];
        nw[i]  = fminf(fmaxf(wgt[i], LBV), UBV);
    }
    bool done = false;
    #pragma unroll
    for (int it = 0; it < 8; it++) {
        float leftover = 0.f, msum = 0.f;
        float masked[PP];
        #pragma unroll
        for (int i = 0; i < PP; i++) {
            leftover += oldw[i] - nw[i];
            masked[i] = (nw[i] != UBV) ? nw[i] : 0.f;
            msum += masked[i];
        }
        float new2[PP];
        #pragma unroll
        for (int i = 0; i < PP; i++) new2[i] = nw[i] + leftover * masked[i] / msum;
        bool cont = false;
        #pragma unroll
        for (int i = 0; i < PP; i++) cont = cont || (new2[i] > UBV);
        float new3[PP];
        #pragma unroll
        for (int i = 0; i < PP; i++)
            new3[i] = cont ? fminf(fmaxf(new2[i], LBV), UBV) : new2[i];
        if (!done) {
            #pragma unroll
            for (int i = 0; i < PP; i++) { oldw[i] = new2[i]; nw[i] = new3[i]; }
        }
        done = done || !cont;
    }

    // wealth
    const float x1v = x1[base + tid];
    float wealth = 0.f;
    #pragma unroll
    for (int i = 0; i < PP; i++) wealth += x1v * nw[i] * (1.f + r[i]) * 1.03f;
    out_wealth[base + tid] = wealth;

    // curr_cov[i][j] = omega + alpha*x2[i][j] + beta*Ce[j]^2, written in place into
    // this thread's own shared row (no cross-thread hazard), then coalesced store.
    #pragma unroll
    for (int i = 0; i < PP; i++)
        #pragma unroll
        for (int j = 0; j < PP; j++)
            s_x2[tid * 25 + i * PP + j] = 0.05f + 0.1f * m2[i * PP + j] + 0.05f * ce[j] * ce[j];
    __syncthreads();

    float* __restrict__ covg = out_cov + base * 25;
    #pragma unroll 4
    for (int j = tid; j < BLK * 25; j += BLK) covg[j] = s_x2[j];
}

extern "C" void kernel_launch(void* const* d_in, const int* in_sizes, int n_in,
                              void* d_out, int out_size) {
    const float* x1  = (const float*)d_in[0];   // (B,)
    const float* x2  = (const float*)d_in[1];   // (B,5,5)
    const float* eps = (const float*)d_in[2];   // (4,B,5)
    const float* W   = (const float*)d_in[3];   // (4,3,5,5)
    float* out = (float*)d_out;                 // [wealth(B) | curr_cov(B*25)]

    const int B = in_sizes[0];
    float* out_wealth = out;
    float* out_cov    = out + B;

    portfolio_kernel<<<B / BLK, BLK>>>(x1, x2, eps, W, out_wealth, out_cov, B);
}

// round 4
// speedup vs baseline: 2.9390x; 2.9390x over previous
#include <cuda_runtime.h>
#include <cuda_bf16.h>
#include <cstdint>

#define PP 5
#define BLK 256
#define UBV 0.5f
#define LBV 0.0f

__device__ __forceinline__ float tanh_fast(float x) {
    float y;
    asm("tanh.approx.f32 %0, %1;" : "=f"(y) : "f"(x));
    return y;
}

__global__ __launch_bounds__(BLK) void portfolio_kernel(
    const float* __restrict__ x1,    // (B,)
    const float* __restrict__ x2,    // (B,5,5)
    const float* __restrict__ eps,   // (4,B,5)
    const float* __restrict__ W,     // (4,3,5,5)
    float* __restrict__ out_wealth,  // (B,)
    float* __restrict__ out_cov,     // (B,5,5)
    int B, int vec_ok)
{
    // 16B alignment is REQUIRED for the float4 paths. Without it the shared
    // allocator can place these at a 4B-aligned offset -> LDS.128 trap
    // (this was the R2/R3 "misaligned address").
    __shared__ __align__(16) float s_x2[BLK * 25];  // staged x2, rewritten as curr_cov
    __shared__ __align__(16) float s_eps[BLK * 5];  // staged eps[3]
    __shared__ float s_w[75];                        // W[3]: 3 matrices of 5x5

    const int tid = threadIdx.x;
    const long long base = (long long)blockIdx.x * BLK;

    if (tid < 75) s_w[tid] = W[3 * 75 + tid];

    // Coalesced staging of this block's x2 tile and eps[3] tile.
    // vec_ok: uniform host flag — float4 only when global pointers are 16B-aligned.
    const float* __restrict__ x2g  = x2 + base * 25;
    const float* __restrict__ epsg = eps + (long long)3 * B * PP + base * PP;
    if (vec_ok) {
        const float4* __restrict__ g4 = (const float4*)x2g;
        float4* s4 = (float4*)s_x2;
        #pragma unroll
        for (int j = tid; j < BLK * 25 / 4; j += BLK) s4[j] = g4[j];
        const float4* __restrict__ e4 = (const float4*)epsg;
        float4* se4 = (float4*)s_eps;
        for (int j = tid; j < BLK * 5 / 4; j += BLK) se4[j] = e4[j];
    } else {
        #pragma unroll 4
        for (int j = tid; j < BLK * 25; j += BLK) s_x2[j] = x2g[j];
        for (int j = tid; j < BLK * 5; j += BLK) s_eps[j] = epsg[j];
    }
    __syncthreads();

    // Ce = x2_row @ eps3  (stride-25 shared reads: 25 coprime 32 -> conflict-free)
    float e[PP];
    #pragma unroll
    for (int i = 0; i < PP; i++) e[i] = s_eps[tid * PP + i];

    float ce[PP];
    {
        float m2[25];
        #pragma unroll
        for (int i = 0; i < 25; i++) m2[i] = s_x2[tid * 25 + i];
        #pragma unroll
        for (int i = 0; i < PP; i++) {
            float s = 0.f;
            #pragma unroll
            for (int j = 0; j < PP; j++) s += m2[i * PP + j] * e[j];
            ce[i] = s;
        }
        // curr_cov = omega + alpha*x2 + beta*Ce[j]^2 — write into own shared row
        // NOW so the 25 m2 registers die before the MLP (register pressure).
        float cb[PP];
        #pragma unroll
        for (int j = 0; j < PP; j++) cb[j] = 0.05f + 0.05f * ce[j] * ce[j];
        #pragma unroll
        for (int i = 0; i < PP; i++)
            #pragma unroll
            for (int j = 0; j < PP; j++)
                s_x2[tid * 25 + i * PP + j] = fmaf(0.1f, m2[i * PP + j], cb[j]);
    }

    // R = mu + Ce ; h = R then 3x tanh(h @ W_l^T)
    float r[PP], h[PP];
    #pragma unroll
    for (int i = 0; i < PP; i++) { r[i] = 0.01f + ce[i]; h[i] = r[i]; }
    #pragma unroll
    for (int l = 0; l < 3; l++) {
        float t[PP];
        #pragma unroll
        for (int i = 0; i < PP; i++) {
            float s = 0.f;
            #pragma unroll
            for (int j = 0; j < PP; j++) s += h[j] * s_w[l * 25 + i * PP + j];
            t[i] = tanh_fast(s);
        }
        #pragma unroll
        for (int i = 0; i < PP; i++) h[i] = t[i];
    }

    // softmax with max subtraction, single fast reciprocal
    float mx = h[0];
    #pragma unroll
    for (int i = 1; i < PP; i++) mx = fmaxf(mx, h[i]);
    float ssum = 0.f;
    float wgt[PP];
    #pragma unroll
    for (int i = 0; i < PP; i++) { wgt[i] = __expf(h[i] - mx); ssum += wgt[i]; }
    const float sinv = __fdividef(1.f, ssum);
    #pragma unroll
    for (int i = 0; i < PP; i++) wgt[i] *= sinv;

    // --- rebalance: semantics-exact replication of the 8-iter scan.
    // Once cont==false the reference freezes this row, so breaking is exact.
    float oldw[PP], nw[PP];
    #pragma unroll
    for (int i = 0; i < PP; i++) {
        oldw[i] = wgt[i];
        nw[i]  = fminf(fmaxf(wgt[i], LBV), UBV);
    }
    for (int it = 0; it < 8; it++) {
        float leftover = 0.f, msum = 0.f;
        float masked[PP];
        #pragma unroll
        for (int i = 0; i < PP; i++) {
            leftover += oldw[i] - nw[i];
            masked[i] = (nw[i] != UBV) ? nw[i] : 0.f;
            msum += masked[i];
        }
        const float scale = __fdividef(leftover, msum);
        float new2[PP];
        bool cont = false;
        #pragma unroll
        for (int i = 0; i < PP; i++) {
            new2[i] = fmaf(scale, masked[i], nw[i]);
            cont = cont || (new2[i] > UBV);
        }
        #pragma unroll
        for (int i = 0; i < PP; i++) {
            oldw[i] = new2[i];
            nw[i]   = cont ? fminf(fmaxf(new2[i], LBV), UBV) : new2[i];
        }
        if (!cont) break;
    }

    // wealth
    const float x1v = x1[base + tid];
    float wealth = 0.f;
    #pragma unroll
    for (int i = 0; i < PP; i++) wealth += x1v * nw[i] * (1.f + r[i]) * 1.03f;
    out_wealth[base + tid] = wealth;

    __syncthreads();
    // Coalesced store of curr_cov
    float* __restrict__ covg = out_cov + base * 25;
    if (vec_ok) {
        float4* __restrict__ c4 = (float4*)covg;
        const float4* s4 = (const float4*)s_x2;
        #pragma unroll
        for (int j = tid; j < BLK * 25 / 4; j += BLK) c4[j] = s4[j];
    } else {
        #pragma unroll 4
        for (int j = tid; j < BLK * 25; j += BLK) covg[j] = s_x2[j];
    }
}

extern "C" void kernel_launch(void* const* d_in, const int* in_sizes, int n_in,
                              void* d_out, int out_size) {
    const float* x1  = (const float*)d_in[0];   // (B,)
    const float* x2  = (const float*)d_in[1];   // (B,5,5)
    const float* eps = (const float*)d_in[2];   // (4,B,5)
    const float* W   = (const float*)d_in[3];   // (4,3,5,5)
    float* out = (float*)d_out;                 // [wealth(B) | curr_cov(B*25)]

    const int B = in_sizes[0];
    float* out_wealth = out;
    float* out_cov    = out + B;

    // Vector path only if every float4-accessed global stream is 16B aligned.
    // (B is a multiple of BLK=256, so all in-kernel offsets preserve alignment.)
    const int vec_ok =
        (((uintptr_t)x2      & 15) == 0) &&
        (((uintptr_t)eps     & 15) == 0) &&
        (((uintptr_t)out_cov & 15) == 0) ? 1 : 0;

    portfolio_kernel<<<B / BLK, BLK>>>(x1, x2, eps, W, out_wealth, out_cov, B, vec_ok);
}

// round 7
// speedup vs baseline: 4.0125x; 1.3653x over previous
#include <cuda_runtime.h>
#include <cuda_bf16.h>
#include <cstdint>

#define PP 5
#define BLK 256
#define UBV 0.5f
#define LBV 0.0f

__device__ __forceinline__ float tanh_fast(float x) {
    float y;
    asm("tanh.approx.f32 %0, %1;" : "=f"(y) : "f"(x));
    return y;
}

__global__ __launch_bounds__(BLK) void portfolio_kernel(
    const float* __restrict__ x1,    // (B,)
    const float* __restrict__ x2,    // (B,5,5)
    const float* __restrict__ eps,   // (4,B,5)
    const float* __restrict__ W,     // (4,3,5,5)
    float* __restrict__ out_wealth,  // (B,)
    float* __restrict__ out_cov,     // (B,5,5)
    int B, int vec_ok)
{
    // 16B alignment REQUIRED for float4 shared paths (R2/R3 trap without it).
    __shared__ __align__(16) float s_x2[BLK * 25];  // staged x2, rewritten as curr_cov
    __shared__ __align__(16) float s_eps[BLK * 5];  // staged eps[3]
    __shared__ float s_w[75];                        // W[3]: 3 matrices of 5x5

    const int tid = threadIdx.x;
    const long long base = (long long)blockIdx.x * BLK;

    // Prefetch x1 early — independent LDG overlaps the staging latency.
    const float x1v = x1[base + tid];

    if (tid < 75) s_w[tid] = W[3 * 75 + tid];

    // Coalesced staging of this block's x2 tile and eps[3] tile.
    const float* __restrict__ x2g  = x2 + base * 25;
    const float* __restrict__ epsg = eps + (long long)3 * B * PP + base * PP;
    if (vec_ok) {
        const float4* __restrict__ g4 = (const float4*)x2g;
        float4* s4 = (float4*)s_x2;
        #pragma unroll
        for (int j = tid; j < BLK * 25 / 4; j += BLK) s4[j] = g4[j];
        const float4* __restrict__ e4 = (const float4*)epsg;
        float4* se4 = (float4*)s_eps;
        for (int j = tid; j < BLK * 5 / 4; j += BLK) se4[j] = e4[j];
    } else {
        #pragma unroll 4
        for (int j = tid; j < BLK * 25; j += BLK) s_x2[j] = x2g[j];
        for (int j = tid; j < BLK * 5; j += BLK) s_eps[j] = epsg[j];
    }
    __syncthreads();

    // Ce = x2_row @ eps3  (stride-25 shared reads: 25 coprime 32 -> conflict-free)
    float e[PP];
    #pragma unroll
    for (int i = 0; i < PP; i++) e[i] = s_eps[tid * PP + i];

    float ce[PP];
    {
        float m2[25];
        #pragma unroll
        for (int i = 0; i < 25; i++) m2[i] = s_x2[tid * 25 + i];
        #pragma unroll
        for (int i = 0; i < PP; i++) {
            float s = 0.f;
            #pragma unroll
            for (int j = 0; j < PP; j++) s += m2[i * PP + j] * e[j];
            ce[i] = s;
        }
        // curr_cov = omega + alpha*x2 + beta*Ce[j]^2 — write into own shared row
        // NOW so the 25 m2 registers die before the MLP (register pressure).
        float cb[PP];
        #pragma unroll
        for (int j = 0; j < PP; j++) cb[j] = 0.05f + 0.05f * ce[j] * ce[j];
        #pragma unroll
        for (int i = 0; i < PP; i++)
            #pragma unroll
            for (int j = 0; j < PP; j++)
                s_x2[tid * 25 + i * PP + j] = fmaf(0.1f, m2[i * PP + j], cb[j]);
    }

    // R = mu + Ce ; h = R then 3x tanh(h @ W_l^T)
    float r[PP], h[PP];
    #pragma unroll
    for (int i = 0; i < PP; i++) { r[i] = 0.01f + ce[i]; h[i] = r[i]; }
    #pragma unroll
    for (int l = 0; l < 3; l++) {
        float t[PP];
        #pragma unroll
        for (int i = 0; i < PP; i++) {
            float s = 0.f;
            #pragma unroll
            for (int j = 0; j < PP; j++) s += h[j] * s_w[l * 25 + i * PP + j];
            t[i] = tanh_fast(s);
        }
        #pragma unroll
        for (int i = 0; i < PP; i++) h[i] = t[i];
    }

    // softmax with max subtraction, single fast reciprocal
    float mx = h[0];
    #pragma unroll
    for (int i = 1; i < PP; i++) mx = fmaxf(mx, h[i]);
    float ssum = 0.f;
    float wgt[PP];
    #pragma unroll
    for (int i = 0; i < PP; i++) { wgt[i] = __expf(h[i] - mx); ssum += wgt[i]; }
    const float sinv = __fdividef(1.f, ssum);
    #pragma unroll
    for (int i = 0; i < PP; i++) wgt[i] *= sinv;

    // --- rebalance: semantics-exact replication of the 8-iter scan.
    // Once cont==false the reference freezes this row, so breaking is exact.
    float oldw[PP], nw[PP];
    #pragma unroll
    for (int i = 0; i < PP; i++) {
        oldw[i] = wgt[i];
        nw[i]  = fminf(fmaxf(wgt[i], LBV), UBV);
    }
    for (int it = 0; it < 8; it++) {
        float leftover = 0.f, msum = 0.f;
        float masked[PP];
        #pragma unroll
        for (int i = 0; i < PP; i++) {
            leftover += oldw[i] - nw[i];
            masked[i] = (nw[i] != UBV) ? nw[i] : 0.f;
            msum += masked[i];
        }
        const float scale = __fdividef(leftover, msum);
        float new2[PP];
        bool cont = false;
        #pragma unroll
        for (int i = 0; i < PP; i++) {
            new2[i] = fmaf(scale, masked[i], nw[i]);
            cont = cont || (new2[i] > UBV);
        }
        #pragma unroll
        for (int i = 0; i < PP; i++) {
            oldw[i] = new2[i];
            nw[i]   = cont ? fminf(fmaxf(new2[i], LBV), UBV) : new2[i];
        }
        if (!cont) break;
    }

    // wealth — evict-first store (output is never re-read; keep L2 for inputs)
    float wealth = 0.f;
    #pragma unroll
    for (int i = 0; i < PP; i++) wealth += x1v * nw[i] * (1.f + r[i]) * 1.03f;
    __stcs(out_wealth + base + tid, wealth);

    __syncthreads();
    // Coalesced evict-first store of curr_cov. Streaming the 54.6 MB of output
    // keeps the 65 MB input set resident in L2 across graph replays.
    float* __restrict__ covg = out_cov + base * 25;
    if (vec_ok) {
        float4* __restrict__ c4 = (float4*)covg;
        const float4* s4 = (const float4*)s_x2;
        #pragma unroll
        for (int j = tid; j < BLK * 25 / 4; j += BLK) __stcs(c4 + j, s4[j]);
    } else {
        #pragma unroll 4
        for (int j = tid; j < BLK * 25; j += BLK) __stcs(covg + j, s_x2[j]);
    }
}

extern "C" void kernel_launch(void* const* d_in, const int* in_sizes, int n_in,
                              void* d_out, int out_size) {
    const float* x1  = (const float*)d_in[0];   // (B,)
    const float* x2  = (const float*)d_in[1];   // (B,5,5)
    const float* eps = (const float*)d_in[2];   // (4,B,5)
    const float* W   = (const float*)d_in[3];   // (4,3,5,5)
    float* out = (float*)d_out;                 // [wealth(B) | curr_cov(B*25)]

    const int B = in_sizes[0];
    float* out_wealth = out;
    float* out_cov    = out + B;

    // Vector path only if every float4-accessed global stream is 16B aligned.
    // (B is a multiple of BLK=256, so all in-kernel offsets preserve alignment.)
    const int vec_ok =
        (((uintptr_t)x2      & 15) == 0) &&
        (((uintptr_t)eps     & 15) == 0) &&
        (((uintptr_t)out_cov & 15) == 0) ? 1 : 0;

    portfolio_kernel<<<B / BLK, BLK>>>(x1, x2, eps, W, out_wealth, out_cov, B, vec_ok);
}